// round 1
// baseline (speedup 1.0000x reference)
#include <cuda_runtime.h>

// ---------------------------------------------------------------------------
// GraphLayer: 3x relational attention (fp32) + output projection, GB300.
//   T_r  = node @ W_r                  [8,1024,768]
//   S_r  = mask(T_r @ node^T)          [8,1024,1024]
//   A_r  = softmax_rows(S_r)
//   O_r  = A_r @ node  -> WCAT chunk   [8,1024,2304]
//   out  = WCAT @ params               [8,1024,768]
// All GEMM dims are multiples of 128 -> no bounds checks anywhere.
// fp32 accuracy is REQUIRED: scores std ~768 => softmax ~one-hot => argmax
// stability needs near-fp32 score precision. Inner loops use fma.rn.f32x2
// (FFMA2) to double fp32 throughput on sm_103a.
// ---------------------------------------------------------------------------

#define BM 128
#define BN 128
#define BK 8
#define TM 8
#define TN 8
#define NTHREADS 256

typedef unsigned long long u64;

__device__ __forceinline__ u64 pack2(float lo, float hi) {
    u64 r;
    asm("mov.b64 %0, {%1,%2};" : "=l"(r) : "f"(lo), "f"(hi));
    return r;
}
__device__ __forceinline__ void fma2(u64& d, u64 a, u64 b) {
    asm("fma.rn.f32x2 %0, %1, %2, %3;" : "=l"(d) : "l"(a), "l"(b), "l"(d));
}
__device__ __forceinline__ float2 unpack2(u64 v) {
    float2 r;
    asm("mov.b64 {%0,%1}, %2;" : "=f"(r.x), "=f"(r.y) : "l"(v));
    return r;
}

// Scratch (device globals: no runtime allocation allowed).
__device__ float g_T[18874368];   // 3*8*1024*768
__device__ float g_S[25165824];   // 3*8*1024*1024
__device__ float g_W[18874368];   // 8*1024*2304

// ---------------------------------------------------------------------------
// Tiled SGEMM: C[M,N] = A[M,K] * op(B), row-major, batched over grid.z.
//   TRANSB=false: B is [K,N] (NN).  TRANSB=true: B is [N,K] (NT).
//   MASK=true: epilogue C = (adj==1) ? C : -1e7f  (adj ld == ldc).
// 128x128x8 tiles, double-buffered smem, 8x8 microtile, f32x2 FMAs.
// ---------------------------------------------------------------------------
template <bool TRANSB, bool MASK>
__global__ void __launch_bounds__(NTHREADS, 2)
sgemm_kernel(const float* __restrict__ Ag, const float* __restrict__ Bg,
             float* __restrict__ Cg, const int* __restrict__ AdjG,
             int K, int lda, int ldb, int ldc,
             long long sA, long long sB, long long sC, long long sAdj) {
    __shared__ __align__(16) float As[2][BK][BM];
    __shared__ __align__(16) float Bs[2][BK][BN];

    const int tid = threadIdx.x;
    const int bx = blockIdx.x, by = blockIdx.y, bz = blockIdx.z;

    const float* A = Ag + (long long)bz * sA;
    const float* B = Bg + (long long)bz * sB;
    float* C = Cg + (long long)bz * sC;

    const int arow = tid >> 1;       // 0..127
    const int akc = (tid & 1) * 4;   // 0 or 4
    const float* Aload = A + (long long)(by * BM + arow) * lda + akc;

    const float* Bload;
    int bkr = 0, bcol = 0;
    if (TRANSB) {
        Bload = B + (long long)(bx * BN + arow) * ldb + akc;
    } else {
        bkr = tid >> 5;              // 0..7
        bcol = (tid & 31) * 4;       // 0..124
        Bload = B + (long long)bkr * ldb + bx * BN + bcol;
    }

    const int nk = K / BK;

    // Prologue: stage tile 0 into buffer 0.
    {
        float4 ra = *(const float4*)(Aload);
        As[0][akc + 0][arow] = ra.x;
        As[0][akc + 1][arow] = ra.y;
        As[0][akc + 2][arow] = ra.z;
        As[0][akc + 3][arow] = ra.w;
        if (TRANSB) {
            float4 rb = *(const float4*)(Bload);
            Bs[0][akc + 0][arow] = rb.x;
            Bs[0][akc + 1][arow] = rb.y;
            Bs[0][akc + 2][arow] = rb.z;
            Bs[0][akc + 3][arow] = rb.w;
        } else {
            *(float4*)&Bs[0][bkr][bcol] = *(const float4*)(Bload);
        }
    }
    __syncthreads();

    const int tx = tid & 15, ty = tid >> 4;
    u64 acc[TM][TN / 2];
#pragma unroll
    for (int i = 0; i < TM; i++)
#pragma unroll
        for (int j = 0; j < TN / 2; j++) acc[i][j] = 0ull;

    for (int kt = 0; kt < nk; kt++) {
        const int buf = kt & 1;
        float4 na, nb;
        const bool more = (kt + 1 < nk);
        if (more) {
            na = *(const float4*)(Aload + (kt + 1) * BK);
            if (TRANSB)
                nb = *(const float4*)(Bload + (kt + 1) * BK);
            else
                nb = *(const float4*)(Bload + (long long)(kt + 1) * BK * ldb);
        }

#pragma unroll
        for (int k = 0; k < BK; k++) {
            float4 a0 = *(const float4*)&As[buf][k][ty * TM];
            float4 a1 = *(const float4*)&As[buf][k][ty * TM + 4];
            ulonglong2 bA = *(const ulonglong2*)&Bs[buf][k][tx * TN];
            ulonglong2 bB = *(const ulonglong2*)&Bs[buf][k][tx * TN + 4];
            const u64 b0 = bA.x, b1 = bA.y, b2 = bB.x, b3 = bB.y;
            float av[8] = {a0.x, a0.y, a0.z, a0.w, a1.x, a1.y, a1.z, a1.w};
#pragma unroll
            for (int i = 0; i < 8; i++) {
                u64 ap = pack2(av[i], av[i]);
                fma2(acc[i][0], ap, b0);
                fma2(acc[i][1], ap, b1);
                fma2(acc[i][2], ap, b2);
                fma2(acc[i][3], ap, b3);
            }
        }

        if (more) {
            const int nbuf = buf ^ 1;
            As[nbuf][akc + 0][arow] = na.x;
            As[nbuf][akc + 1][arow] = na.y;
            As[nbuf][akc + 2][arow] = na.z;
            As[nbuf][akc + 3][arow] = na.w;
            if (TRANSB) {
                Bs[nbuf][akc + 0][arow] = nb.x;
                Bs[nbuf][akc + 1][arow] = nb.y;
                Bs[nbuf][akc + 2][arow] = nb.z;
                Bs[nbuf][akc + 3][arow] = nb.w;
            } else {
                *(float4*)&Bs[nbuf][bkr][bcol] = nb;
            }
        }
        __syncthreads();
    }

    // Epilogue
    const int crow0 = by * BM + ty * TM;
    const int ccol = bx * BN + tx * TN;
#pragma unroll
    for (int i = 0; i < TM; i++) {
        float o[8];
#pragma unroll
        for (int j = 0; j < TN / 2; j++) {
            float2 f = unpack2(acc[i][j]);
            o[2 * j] = f.x;
            o[2 * j + 1] = f.y;
        }
        const long long roff = (long long)(crow0 + i) * ldc + ccol;
        if (MASK) {
            const int* adj = AdjG + (long long)bz * sAdj + roff;
            int4 m0 = *(const int4*)adj;
            int4 m1 = *(const int4*)(adj + 4);
            o[0] = (m0.x == 1) ? o[0] : -1e7f;
            o[1] = (m0.y == 1) ? o[1] : -1e7f;
            o[2] = (m0.z == 1) ? o[2] : -1e7f;
            o[3] = (m0.w == 1) ? o[3] : -1e7f;
            o[4] = (m1.x == 1) ? o[4] : -1e7f;
            o[5] = (m1.y == 1) ? o[5] : -1e7f;
            o[6] = (m1.z == 1) ? o[6] : -1e7f;
            o[7] = (m1.w == 1) ? o[7] : -1e7f;
        }
        float4 s0 = {o[0], o[1], o[2], o[3]};
        float4 s1 = {o[4], o[5], o[6], o[7]};
        *(float4*)(C + roff) = s0;
        *(float4*)(C + roff + 4) = s1;
    }
}

// ---------------------------------------------------------------------------
// Row softmax over rows of length 1024. One block (256 threads) per row.
// Matches jax.nn.softmax: x - max -> exp -> / sum. Fully-masked rows come
// out uniform, same as the reference.
// ---------------------------------------------------------------------------
__global__ void softmax_kernel(float* __restrict__ S) {
    const long long row = blockIdx.x;
    float* p = S + row * 1024;
    const int t = threadIdx.x;
    const int warp = t >> 5, lane = t & 31;

    float4 v = ((const float4*)p)[t];
    float m = fmaxf(fmaxf(v.x, v.y), fmaxf(v.z, v.w));
#pragma unroll
    for (int o = 16; o; o >>= 1) m = fmaxf(m, __shfl_xor_sync(0xffffffffu, m, o));

    __shared__ float redm[8];
    __shared__ float reds[8];
    if (lane == 0) redm[warp] = m;
    __syncthreads();
    float mm = redm[0];
#pragma unroll
    for (int i = 1; i < 8; i++) mm = fmaxf(mm, redm[i]);

    v.x = expf(v.x - mm);
    v.y = expf(v.y - mm);
    v.z = expf(v.z - mm);
    v.w = expf(v.w - mm);
    float s = v.x + v.y + v.z + v.w;
#pragma unroll
    for (int o = 16; o; o >>= 1) s += __shfl_xor_sync(0xffffffffu, s, o);
    if (lane == 0) reds[warp] = s;
    __syncthreads();
    float ss = reds[0];
#pragma unroll
    for (int i = 1; i < 8; i++) ss += reds[i];

    const float inv = 1.0f / ss;
    v.x *= inv;
    v.y *= inv;
    v.z *= inv;
    v.w *= inv;
    ((float4*)p)[t] = v;
}

// ---------------------------------------------------------------------------
extern "C" void kernel_launch(void* const* d_in, const int* in_sizes, int n_in,
                              void* d_out, int out_size) {
    const float* node = (const float*)d_in[0];
    const int* adj[3] = {(const int*)d_in[1], (const int*)d_in[2],
                         (const int*)d_in[3]};
    const float* W[3] = {(const float*)d_in[4], (const float*)d_in[5],
                         (const float*)d_in[6]};
    const float* P = (const float*)d_in[7];
    float* out = (float*)d_out;

    void *pT, *pS, *pW;
    cudaGetSymbolAddress(&pT, g_T);
    cudaGetSymbolAddress(&pS, g_S);
    cudaGetSymbolAddress(&pW, g_W);
    float* T = (float*)pT;
    float* S = (float*)pS;
    float* Wc = (float*)pW;

    const long long TB = 8ll * 1024 * 768;   // per-relation T block
    const long long SB = 8ll * 1024 * 1024;  // per-relation S block
    dim3 blk(NTHREADS);

    // Stage 1: T_r = node @ W_r   (M=8192, N=768, K=768)
    for (int r = 0; r < 3; r++)
        sgemm_kernel<false, false><<<dim3(6, 64, 1), blk>>>(
            node, W[r], T + r * TB, nullptr, 768, 768, 768, 768, 0, 0, 0, 0);

    // Stage 2: S_r = mask(T_r @ node^T) per batch (M=1024, N=1024, K=768)
    for (int r = 0; r < 3; r++)
        sgemm_kernel<true, true><<<dim3(8, 8, 8), blk>>>(
            T + r * TB, node, S + r * SB, adj[r], 768, 768, 768, 1024,
            1024ll * 768, 1024ll * 768, 1024ll * 1024, 1024ll * 1024);

    // Stage 3: row softmax over all 3*8*1024 rows
    softmax_kernel<<<3 * 8 * 1024, 256>>>(S);

    // Stage 4: O_r = A_r @ node -> WCAT[:, :, r*768:(r+1)*768]
    for (int r = 0; r < 3; r++)
        sgemm_kernel<false, false><<<dim3(6, 8, 8), blk>>>(
            S + r * SB, node, Wc + r * 768, nullptr, 1024, 1024, 768, 2304,
            1024ll * 1024, 1024ll * 768, 1024ll * 2304, 0);

    // Stage 5: out = WCAT @ params  (M=8192, N=768, K=2304)
    sgemm_kernel<false, false><<<dim3(6, 64, 1), blk>>>(
        Wc, P, out, nullptr, 2304, 2304, 768, 768, 0, 0, 0, 0);
}

// round 3
// speedup vs baseline: 1.1886x; 1.1886x over previous
#include <cuda_runtime.h>

// ---------------------------------------------------------------------------
// GraphLayer: 3x relational attention (fp32) + output projection, GB300.
// Round 3 (= Round 2 re-bench after infra flake): smem-crossbar relief.
// 16x8 per-thread microtile, 128-thread CTAs, accumulators paired along M
// via fma.rn.f32x2 so A fragments come out of shared memory pre-paired
// (no pack movs on the A side). 0.75 B smem / MAC vs 1.0 before; the fma
// pipe should become the binding resource.
// ---------------------------------------------------------------------------

#define NT 128   // threads per block
#define BK 8

typedef unsigned long long u64;

__device__ __forceinline__ u64 pack2(float lo, float hi) {
    u64 r;
    asm("mov.b64 %0, {%1,%2};" : "=l"(r) : "f"(lo), "f"(hi));
    return r;
}
__device__ __forceinline__ void fma2(u64& d, u64 a, u64 b) {
    asm("fma.rn.f32x2 %0, %1, %2, %3;" : "=l"(d) : "l"(a), "l"(b), "l"(d));
}
__device__ __forceinline__ float2 unpack2(u64 v) {
    float2 r;
    asm("mov.b64 {%0,%1}, %2;" : "=f"(r.x), "=f"(r.y) : "l"(v));
    return r;
}

// Scratch (device globals: no runtime allocation allowed).
__device__ float g_T[18874368];   // 3*8*1024*768
__device__ float g_S[25165824];   // 3*8*1024*1024
__device__ float g_W[18874368];   // 8*1024*2304

// ---------------------------------------------------------------------------
// Tiled SGEMM: C[M,N] = A[M,K] * op(B), row-major, batched over grid.z.
//   TRANSB=false: B is [K,N] (NN).  TRANSB=true: B is [N,K] (NT).
//   MASK=true: epilogue C = (adj==1) ? C : -1e7f  (adj ld == ldc).
// 128x128x8 block tile, double-buffered smem, 128 threads, 16x8 microtile.
// Thread (tx = tid&15, my = tid>>4) owns rows [my*16, my*16+16) as 8 f32x2
// M-pairs and cols [tx*8, tx*8+8).
// ---------------------------------------------------------------------------
template <bool TRANSB, bool MASK>
__global__ void __launch_bounds__(NT, 2)
sgemm_kernel(const float* __restrict__ Ag, const float* __restrict__ Bg,
             float* __restrict__ Cg, const int* __restrict__ AdjG,
             int K, int lda, int ldb, int ldc,
             long long sA, long long sB, long long sC, long long sAdj) {
    __shared__ __align__(16) float As[2][BK][128];
    __shared__ __align__(16) float Bs[2][BK][128];

    const int tid = threadIdx.x;
    const int bx = blockIdx.x, by = blockIdx.y, bz = blockIdx.z;

    const float* A = Ag + (long long)bz * sA;
    const float* B = Bg + (long long)bz * sB;
    float* C = Cg + (long long)bz * sC;

    // Staging pointers: each thread loads one 8-float segment of A and one
    // 8-float segment of B per k-tile (2x float4 each).
    const float* Aload = A + (long long)(by * 128 + tid) * lda;

    const float* Bload;
    int bkr = 0, bcol = 0;
    long long bstep;
    if (TRANSB) {
        Bload = B + (long long)(bx * 128 + tid) * ldb;
        bstep = BK;
    } else {
        bkr = tid >> 4;              // 0..7 (k row)
        bcol = (tid & 15) * 8;       // 0..120
        Bload = B + (long long)bkr * ldb + bx * 128 + bcol;
        bstep = (long long)BK * ldb;
    }

    const int nk = K / BK;

    // Prologue: stage tile 0 into buffer 0.
    {
        float4 a0 = *(const float4*)(Aload);
        float4 a1 = *(const float4*)(Aload + 4);
        As[0][0][tid] = a0.x; As[0][1][tid] = a0.y;
        As[0][2][tid] = a0.z; As[0][3][tid] = a0.w;
        As[0][4][tid] = a1.x; As[0][5][tid] = a1.y;
        As[0][6][tid] = a1.z; As[0][7][tid] = a1.w;
        if (TRANSB) {
            float4 b0 = *(const float4*)(Bload);
            float4 b1 = *(const float4*)(Bload + 4);
            Bs[0][0][tid] = b0.x; Bs[0][1][tid] = b0.y;
            Bs[0][2][tid] = b0.z; Bs[0][3][tid] = b0.w;
            Bs[0][4][tid] = b1.x; Bs[0][5][tid] = b1.y;
            Bs[0][6][tid] = b1.z; Bs[0][7][tid] = b1.w;
        } else {
            *(float4*)&Bs[0][bkr][bcol] = *(const float4*)(Bload);
            *(float4*)&Bs[0][bkr][bcol + 4] = *(const float4*)(Bload + 4);
        }
    }
    __syncthreads();

    const int tx = tid & 15, my = tid >> 4;

    u64 acc[8][8];
#pragma unroll
    for (int p = 0; p < 8; p++)
#pragma unroll
        for (int j = 0; j < 8; j++) acc[p][j] = 0ull;

    const float* Anext = Aload + BK;
    const float* Bnext = Bload + bstep;

    for (int kt = 0; kt < nk; kt++) {
        const int buf = kt & 1;
        float4 na0, na1, nb0, nb1;
        const bool more = (kt + 1 < nk);
        if (more) {
            na0 = *(const float4*)(Anext);
            na1 = *(const float4*)(Anext + 4);
            nb0 = *(const float4*)(Bnext);
            nb1 = *(const float4*)(Bnext + 4);
            Anext += BK;
            Bnext += bstep;
        }

#pragma unroll
        for (int k = 0; k < BK; k++) {
            // A: 16 consecutive M values for this thread, pre-paired as u64.
            ulonglong2 aA = *(const ulonglong2*)&As[buf][k][my * 16];
            ulonglong2 aB = *(const ulonglong2*)&As[buf][k][my * 16 + 4];
            ulonglong2 aC = *(const ulonglong2*)&As[buf][k][my * 16 + 8];
            ulonglong2 aD = *(const ulonglong2*)&As[buf][k][my * 16 + 12];
            u64 ap[8] = {aA.x, aA.y, aB.x, aB.y, aC.x, aC.y, aD.x, aD.y};
            // B: 8 scalars, duplicated into f32x2 lanes.
            float4 b0 = *(const float4*)&Bs[buf][k][tx * 8];
            float4 b1 = *(const float4*)&Bs[buf][k][tx * 8 + 4];
            u64 bd[8];
            bd[0] = pack2(b0.x, b0.x); bd[1] = pack2(b0.y, b0.y);
            bd[2] = pack2(b0.z, b0.z); bd[3] = pack2(b0.w, b0.w);
            bd[4] = pack2(b1.x, b1.x); bd[5] = pack2(b1.y, b1.y);
            bd[6] = pack2(b1.z, b1.z); bd[7] = pack2(b1.w, b1.w);
#pragma unroll
            for (int p = 0; p < 8; p++) {
#pragma unroll
                for (int j = 0; j < 8; j++) fma2(acc[p][j], ap[p], bd[j]);
            }
        }

        if (more) {
            const int nbuf = buf ^ 1;
            As[nbuf][0][tid] = na0.x; As[nbuf][1][tid] = na0.y;
            As[nbuf][2][tid] = na0.z; As[nbuf][3][tid] = na0.w;
            As[nbuf][4][tid] = na1.x; As[nbuf][5][tid] = na1.y;
            As[nbuf][6][tid] = na1.z; As[nbuf][7][tid] = na1.w;
            if (TRANSB) {
                Bs[nbuf][0][tid] = nb0.x; Bs[nbuf][1][tid] = nb0.y;
                Bs[nbuf][2][tid] = nb0.z; Bs[nbuf][3][tid] = nb0.w;
                Bs[nbuf][4][tid] = nb1.x; Bs[nbuf][5][tid] = nb1.y;
                Bs[nbuf][6][tid] = nb1.z; Bs[nbuf][7][tid] = nb1.w;
            } else {
                *(float4*)&Bs[nbuf][bkr][bcol] = nb0;
                *(float4*)&Bs[nbuf][bkr][bcol + 4] = nb1;
            }
        }
        __syncthreads();
    }

    // Epilogue: 8 M-pairs x 8 cols -> 16 rows x 8 cols.
    const int row0 = by * 128 + my * 16;
    const int col = bx * 128 + tx * 8;
#pragma unroll
    for (int p = 0; p < 8; p++) {
        float lo[8], hi[8];
#pragma unroll
        for (int j = 0; j < 8; j++) {
            float2 f = unpack2(acc[p][j]);
            lo[j] = f.x;
            hi[j] = f.y;
        }
        const long long r0 = (long long)(row0 + 2 * p) * ldc + col;
        const long long r1 = r0 + ldc;
        if (MASK) {
            const int* adj0 = AdjG + (long long)bz * sAdj + r0;
            const int* adj1 = AdjG + (long long)bz * sAdj + r1;
            int4 m0 = *(const int4*)adj0;
            int4 m1 = *(const int4*)(adj0 + 4);
            int4 m2 = *(const int4*)adj1;
            int4 m3 = *(const int4*)(adj1 + 4);
            lo[0] = (m0.x == 1) ? lo[0] : -1e7f;
            lo[1] = (m0.y == 1) ? lo[1] : -1e7f;
            lo[2] = (m0.z == 1) ? lo[2] : -1e7f;
            lo[3] = (m0.w == 1) ? lo[3] : -1e7f;
            lo[4] = (m1.x == 1) ? lo[4] : -1e7f;
            lo[5] = (m1.y == 1) ? lo[5] : -1e7f;
            lo[6] = (m1.z == 1) ? lo[6] : -1e7f;
            lo[7] = (m1.w == 1) ? lo[7] : -1e7f;
            hi[0] = (m2.x == 1) ? hi[0] : -1e7f;
            hi[1] = (m2.y == 1) ? hi[1] : -1e7f;
            hi[2] = (m2.z == 1) ? hi[2] : -1e7f;
            hi[3] = (m2.w == 1) ? hi[3] : -1e7f;
            hi[4] = (m3.x == 1) ? hi[4] : -1e7f;
            hi[5] = (m3.y == 1) ? hi[5] : -1e7f;
            hi[6] = (m3.z == 1) ? hi[6] : -1e7f;
            hi[7] = (m3.w == 1) ? hi[7] : -1e7f;
        }
        float4 s;
        s = make_float4(lo[0], lo[1], lo[2], lo[3]); *(float4*)(C + r0) = s;
        s = make_float4(lo[4], lo[5], lo[6], lo[7]); *(float4*)(C + r0 + 4) = s;
        s = make_float4(hi[0], hi[1], hi[2], hi[3]); *(float4*)(C + r1) = s;
        s = make_float4(hi[4], hi[5], hi[6], hi[7]); *(float4*)(C + r1 + 4) = s;
    }
}

// ---------------------------------------------------------------------------
// Row softmax over rows of length 1024. One block (256 threads) per row.
// Matches jax.nn.softmax: x - max -> exp -> / sum.
// ---------------------------------------------------------------------------
__global__ void softmax_kernel(float* __restrict__ S) {
    const long long row = blockIdx.x;
    float* p = S + row * 1024;
    const int t = threadIdx.x;
    const int warp = t >> 5, lane = t & 31;

    float4 v = ((const float4*)p)[t];
    float m = fmaxf(fmaxf(v.x, v.y), fmaxf(v.z, v.w));
#pragma unroll
    for (int o = 16; o; o >>= 1) m = fmaxf(m, __shfl_xor_sync(0xffffffffu, m, o));

    __shared__ float redm[8];
    __shared__ float reds[8];
    if (lane == 0) redm[warp] = m;
    __syncthreads();
    float mm = redm[0];
#pragma unroll
    for (int i = 1; i < 8; i++) mm = fmaxf(mm, redm[i]);

    v.x = expf(v.x - mm);
    v.y = expf(v.y - mm);
    v.z = expf(v.z - mm);
    v.w = expf(v.w - mm);
    float s = v.x + v.y + v.z + v.w;
#pragma unroll
    for (int o = 16; o; o >>= 1) s += __shfl_xor_sync(0xffffffffu, s, o);
    if (lane == 0) reds[warp] = s;
    __syncthreads();
    float ss = reds[0];
#pragma unroll
    for (int i = 1; i < 8; i++) ss += reds[i];

    const float inv = 1.0f / ss;
    v.x *= inv;
    v.y *= inv;
    v.z *= inv;
    v.w *= inv;
    ((float4*)p)[t] = v;
}

// ---------------------------------------------------------------------------
extern "C" void kernel_launch(void* const* d_in, const int* in_sizes, int n_in,
                              void* d_out, int out_size) {
    const float* node = (const float*)d_in[0];
    const int* adj[3] = {(const int*)d_in[1], (const int*)d_in[2],
                         (const int*)d_in[3]};
    const float* W[3] = {(const float*)d_in[4], (const float*)d_in[5],
                         (const float*)d_in[6]};
    const float* P = (const float*)d_in[7];
    float* out = (float*)d_out;

    void *pT, *pS, *pW;
    cudaGetSymbolAddress(&pT, g_T);
    cudaGetSymbolAddress(&pS, g_S);
    cudaGetSymbolAddress(&pW, g_W);
    float* T = (float*)pT;
    float* S = (float*)pS;
    float* Wc = (float*)pW;

    const long long TB = 8ll * 1024 * 768;   // per-relation T block
    const long long SB = 8ll * 1024 * 1024;  // per-relation S block
    dim3 blk(NT);

    // Stage 1: T_r = node @ W_r   (M=8192, N=768, K=768)
    for (int r = 0; r < 3; r++)
        sgemm_kernel<false, false><<<dim3(6, 64, 1), blk>>>(
            node, W[r], T + r * TB, nullptr, 768, 768, 768, 768, 0, 0, 0, 0);

    // Stage 2: S_r = mask(T_r @ node^T) per batch (M=1024, N=1024, K=768)
    for (int r = 0; r < 3; r++)
        sgemm_kernel<true, true><<<dim3(8, 8, 8), blk>>>(
            T + r * TB, node, S + r * SB, adj[r], 768, 768, 768, 1024,
            1024ll * 768, 1024ll * 768, 1024ll * 1024, 1024ll * 1024);

    // Stage 3: row softmax over all 3*8*1024 rows
    softmax_kernel<<<3 * 8 * 1024, 256>>>(S);

    // Stage 4: O_r = A_r @ node -> WCAT[:, :, r*768:(r+1)*768]
    for (int r = 0; r < 3; r++)
        sgemm_kernel<false, false><<<dim3(6, 8, 8), blk>>>(
            S + r * SB, node, Wc + r * 768, nullptr, 1024, 1024, 768, 2304,
            1024ll * 1024, 1024ll * 768, 1024ll * 2304, 0);

    // Stage 5: out = WCAT @ params  (M=8192, N=768, K=2304)
    sgemm_kernel<false, false><<<dim3(6, 64, 1), blk>>>(
        Wc, P, out, nullptr, 2304, 2304, 768, 768, 0, 0, 0, 0);
}

// round 5
// speedup vs baseline: 1.1898x; 1.0010x over previous
#include <cuda_runtime.h>

// ---------------------------------------------------------------------------
// GraphLayer: 3x relational attention (fp32) + output projection, GB300.
// Round 3 (= Round 2 re-bench after infra flake): smem-crossbar relief.
// 16x8 per-thread microtile, 128-thread CTAs, accumulators paired along M
// via fma.rn.f32x2 so A fragments come out of shared memory pre-paired
// (no pack movs on the A side). 0.75 B smem / MAC vs 1.0 before; the fma
// pipe should become the binding resource.
// ---------------------------------------------------------------------------

#define NT 128   // threads per block
#define BK 8

typedef unsigned long long u64;

__device__ __forceinline__ u64 pack2(float lo, float hi) {
    u64 r;
    asm("mov.b64 %0, {%1,%2};" : "=l"(r) : "f"(lo), "f"(hi));
    return r;
}
__device__ __forceinline__ void fma2(u64& d, u64 a, u64 b) {
    asm("fma.rn.f32x2 %0, %1, %2, %3;" : "=l"(d) : "l"(a), "l"(b), "l"(d));
}
__device__ __forceinline__ float2 unpack2(u64 v) {
    float2 r;
    asm("mov.b64 {%0,%1}, %2;" : "=f"(r.x), "=f"(r.y) : "l"(v));
    return r;
}

// Scratch (device globals: no runtime allocation allowed).
__device__ float g_T[18874368];   // 3*8*1024*768
__device__ float g_S[25165824];   // 3*8*1024*1024
__device__ float g_W[18874368];   // 8*1024*2304

// ---------------------------------------------------------------------------
// Tiled SGEMM: C[M,N] = A[M,K] * op(B), row-major, batched over grid.z.
//   TRANSB=false: B is [K,N] (NN).  TRANSB=true: B is [N,K] (NT).
//   MASK=true: epilogue C = (adj==1) ? C : -1e7f  (adj ld == ldc).
// 128x128x8 block tile, double-buffered smem, 128 threads, 16x8 microtile.
// Thread (tx = tid&15, my = tid>>4) owns rows [my*16, my*16+16) as 8 f32x2
// M-pairs and cols [tx*8, tx*8+8).
// ---------------------------------------------------------------------------
template <bool TRANSB, bool MASK>
__global__ void __launch_bounds__(NT, 2)
sgemm_kernel(const float* __restrict__ Ag, const float* __restrict__ Bg,
             float* __restrict__ Cg, const int* __restrict__ AdjG,
             int K, int lda, int ldb, int ldc,
             long long sA, long long sB, long long sC, long long sAdj) {
    __shared__ __align__(16) float As[2][BK][128];
    __shared__ __align__(16) float Bs[2][BK][128];

    const int tid = threadIdx.x;
    const int bx = blockIdx.x, by = blockIdx.y, bz = blockIdx.z;

    const float* A = Ag + (long long)bz * sA;
    const float* B = Bg + (long long)bz * sB;
    float* C = Cg + (long long)bz * sC;

    // Staging pointers: each thread loads one 8-float segment of A and one
    // 8-float segment of B per k-tile (2x float4 each).
    const float* Aload = A + (long long)(by * 128 + tid) * lda;

    const float* Bload;
    int bkr = 0, bcol = 0;
    long long bstep;
    if (TRANSB) {
        Bload = B + (long long)(bx * 128 + tid) * ldb;
        bstep = BK;
    } else {
        bkr = tid >> 4;              // 0..7 (k row)
        bcol = (tid & 15) * 8;       // 0..120
        Bload = B + (long long)bkr * ldb + bx * 128 + bcol;
        bstep = (long long)BK * ldb;
    }

    const int nk = K / BK;

    // Prologue: stage tile 0 into buffer 0.
    {
        float4 a0 = *(const float4*)(Aload);
        float4 a1 = *(const float4*)(Aload + 4);
        As[0][0][tid] = a0.x; As[0][1][tid] = a0.y;
        As[0][2][tid] = a0.z; As[0][3][tid] = a0.w;
        As[0][4][tid] = a1.x; As[0][5][tid] = a1.y;
        As[0][6][tid] = a1.z; As[0][7][tid] = a1.w;
        if (TRANSB) {
            float4 b0 = *(const float4*)(Bload);
            float4 b1 = *(const float4*)(Bload + 4);
            Bs[0][0][tid] = b0.x; Bs[0][1][tid] = b0.y;
            Bs[0][2][tid] = b0.z; Bs[0][3][tid] = b0.w;
            Bs[0][4][tid] = b1.x; Bs[0][5][tid] = b1.y;
            Bs[0][6][tid] = b1.z; Bs[0][7][tid] = b1.w;
        } else {
            *(float4*)&Bs[0][bkr][bcol] = *(const float4*)(Bload);
            *(float4*)&Bs[0][bkr][bcol + 4] = *(const float4*)(Bload + 4);
        }
    }
    __syncthreads();

    const int tx = tid & 15, my = tid >> 4;

    u64 acc[8][8];
#pragma unroll
    for (int p = 0; p < 8; p++)
#pragma unroll
        for (int j = 0; j < 8; j++) acc[p][j] = 0ull;

    const float* Anext = Aload + BK;
    const float* Bnext = Bload + bstep;

    for (int kt = 0; kt < nk; kt++) {
        const int buf = kt & 1;
        float4 na0, na1, nb0, nb1;
        const bool more = (kt + 1 < nk);
        if (more) {
            na0 = *(const float4*)(Anext);
            na1 = *(const float4*)(Anext + 4);
            nb0 = *(const float4*)(Bnext);
            nb1 = *(const float4*)(Bnext + 4);
            Anext += BK;
            Bnext += bstep;
        }

#pragma unroll
        for (int k = 0; k < BK; k++) {
            // A: 16 consecutive M values for this thread, pre-paired as u64.
            ulonglong2 aA = *(const ulonglong2*)&As[buf][k][my * 16];
            ulonglong2 aB = *(const ulonglong2*)&As[buf][k][my * 16 + 4];
            ulonglong2 aC = *(const ulonglong2*)&As[buf][k][my * 16 + 8];
            ulonglong2 aD = *(const ulonglong2*)&As[buf][k][my * 16 + 12];
            u64 ap[8] = {aA.x, aA.y, aB.x, aB.y, aC.x, aC.y, aD.x, aD.y};
            // B: 8 scalars, duplicated into f32x2 lanes.
            float4 b0 = *(const float4*)&Bs[buf][k][tx * 8];
            float4 b1 = *(const float4*)&Bs[buf][k][tx * 8 + 4];
            u64 bd[8];
            bd[0] = pack2(b0.x, b0.x); bd[1] = pack2(b0.y, b0.y);
            bd[2] = pack2(b0.z, b0.z); bd[3] = pack2(b0.w, b0.w);
            bd[4] = pack2(b1.x, b1.x); bd[5] = pack2(b1.y, b1.y);
            bd[6] = pack2(b1.z, b1.z); bd[7] = pack2(b1.w, b1.w);
#pragma unroll
            for (int p = 0; p < 8; p++) {
#pragma unroll
                for (int j = 0; j < 8; j++) fma2(acc[p][j], ap[p], bd[j]);
            }
        }

        if (more) {
            const int nbuf = buf ^ 1;
            As[nbuf][0][tid] = na0.x; As[nbuf][1][tid] = na0.y;
            As[nbuf][2][tid] = na0.z; As[nbuf][3][tid] = na0.w;
            As[nbuf][4][tid] = na1.x; As[nbuf][5][tid] = na1.y;
            As[nbuf][6][tid] = na1.z; As[nbuf][7][tid] = na1.w;
            if (TRANSB) {
                Bs[nbuf][0][tid] = nb0.x; Bs[nbuf][1][tid] = nb0.y;
                Bs[nbuf][2][tid] = nb0.z; Bs[nbuf][3][tid] = nb0.w;
                Bs[nbuf][4][tid] = nb1.x; Bs[nbuf][5][tid] = nb1.y;
                Bs[nbuf][6][tid] = nb1.z; Bs[nbuf][7][tid] = nb1.w;
            } else {
                *(float4*)&Bs[nbuf][bkr][bcol] = nb0;
                *(float4*)&Bs[nbuf][bkr][bcol + 4] = nb1;
            }
        }
        __syncthreads();
    }

    // Epilogue: 8 M-pairs x 8 cols -> 16 rows x 8 cols.
    const int row0 = by * 128 + my * 16;
    const int col = bx * 128 + tx * 8;
#pragma unroll
    for (int p = 0; p < 8; p++) {
        float lo[8], hi[8];
#pragma unroll
        for (int j = 0; j < 8; j++) {
            float2 f = unpack2(acc[p][j]);
            lo[j] = f.x;
            hi[j] = f.y;
        }
        const long long r0 = (long long)(row0 + 2 * p) * ldc + col;
        const long long r1 = r0 + ldc;
        if (MASK) {
            const int* adj0 = AdjG + (long long)bz * sAdj + r0;
            const int* adj1 = AdjG + (long long)bz * sAdj + r1;
            int4 m0 = *(const int4*)adj0;
            int4 m1 = *(const int4*)(adj0 + 4);
            int4 m2 = *(const int4*)adj1;
            int4 m3 = *(const int4*)(adj1 + 4);
            lo[0] = (m0.x == 1) ? lo[0] : -1e7f;
            lo[1] = (m0.y == 1) ? lo[1] : -1e7f;
            lo[2] = (m0.z == 1) ? lo[2] : -1e7f;
            lo[3] = (m0.w == 1) ? lo[3] : -1e7f;
            lo[4] = (m1.x == 1) ? lo[4] : -1e7f;
            lo[5] = (m1.y == 1) ? lo[5] : -1e7f;
            lo[6] = (m1.z == 1) ? lo[6] : -1e7f;
            lo[7] = (m1.w == 1) ? lo[7] : -1e7f;
            hi[0] = (m2.x == 1) ? hi[0] : -1e7f;
            hi[1] = (m2.y == 1) ? hi[1] : -1e7f;
            hi[2] = (m2.z == 1) ? hi[2] : -1e7f;
            hi[3] = (m2.w == 1) ? hi[3] : -1e7f;
            hi[4] = (m3.x == 1) ? hi[4] : -1e7f;
            hi[5] = (m3.y == 1) ? hi[5] : -1e7f;
            hi[6] = (m3.z == 1) ? hi[6] : -1e7f;
            hi[7] = (m3.w == 1) ? hi[7] : -1e7f;
        }
        float4 s;
        s = make_float4(lo[0], lo[1], lo[2], lo[3]); *(float4*)(C + r0) = s;
        s = make_float4(lo[4], lo[5], lo[6], lo[7]); *(float4*)(C + r0 + 4) = s;
        s = make_float4(hi[0], hi[1], hi[2], hi[3]); *(float4*)(C + r1) = s;
        s = make_float4(hi[4], hi[5], hi[6], hi[7]); *(float4*)(C + r1 + 4) = s;
    }
}

// ---------------------------------------------------------------------------
// Row softmax over rows of length 1024. One block (256 threads) per row.
// Matches jax.nn.softmax: x - max -> exp -> / sum.
// ---------------------------------------------------------------------------
__global__ void softmax_kernel(float* __restrict__ S) {
    const long long row = blockIdx.x;
    float* p = S + row * 1024;
    const int t = threadIdx.x;
    const int warp = t >> 5, lane = t & 31;

    float4 v = ((const float4*)p)[t];
    float m = fmaxf(fmaxf(v.x, v.y), fmaxf(v.z, v.w));
#pragma unroll
    for (int o = 16; o; o >>= 1) m = fmaxf(m, __shfl_xor_sync(0xffffffffu, m, o));

    __shared__ float redm[8];
    __shared__ float reds[8];
    if (lane == 0) redm[warp] = m;
    __syncthreads();
    float mm = redm[0];
#pragma unroll
    for (int i = 1; i < 8; i++) mm = fmaxf(mm, redm[i]);

    v.x = expf(v.x - mm);
    v.y = expf(v.y - mm);
    v.z = expf(v.z - mm);
    v.w = expf(v.w - mm);
    float s = v.x + v.y + v.z + v.w;
#pragma unroll
    for (int o = 16; o; o >>= 1) s += __shfl_xor_sync(0xffffffffu, s, o);
    if (lane == 0) reds[warp] = s;
    __syncthreads();
    float ss = reds[0];
#pragma unroll
    for (int i = 1; i < 8; i++) ss += reds[i];

    const float inv = 1.0f / ss;
    v.x *= inv;
    v.y *= inv;
    v.z *= inv;
    v.w *= inv;
    ((float4*)p)[t] = v;
}

// ---------------------------------------------------------------------------
extern "C" void kernel_launch(void* const* d_in, const int* in_sizes, int n_in,
                              void* d_out, int out_size) {
    const float* node = (const float*)d_in[0];
    const int* adj[3] = {(const int*)d_in[1], (const int*)d_in[2],
                         (const int*)d_in[3]};
    const float* W[3] = {(const float*)d_in[4], (const float*)d_in[5],
                         (const float*)d_in[6]};
    const float* P = (const float*)d_in[7];
    float* out = (float*)d_out;

    void *pT, *pS, *pW;
    cudaGetSymbolAddress(&pT, g_T);
    cudaGetSymbolAddress(&pS, g_S);
    cudaGetSymbolAddress(&pW, g_W);
    float* T = (float*)pT;
    float* S = (float*)pS;
    float* Wc = (float*)pW;

    const long long TB = 8ll * 1024 * 768;   // per-relation T block
    const long long SB = 8ll * 1024 * 1024;  // per-relation S block
    dim3 blk(NT);

    // Stage 1: T_r = node @ W_r   (M=8192, N=768, K=768)
    for (int r = 0; r < 3; r++)
        sgemm_kernel<false, false><<<dim3(6, 64, 1), blk>>>(
            node, W[r], T + r * TB, nullptr, 768, 768, 768, 768, 0, 0, 0, 0);

    // Stage 2: S_r = mask(T_r @ node^T) per batch (M=1024, N=1024, K=768)
    for (int r = 0; r < 3; r++)
        sgemm_kernel<true, true><<<dim3(8, 8, 8), blk>>>(
            T + r * TB, node, S + r * SB, adj[r], 768, 768, 768, 1024,
            1024ll * 768, 1024ll * 768, 1024ll * 1024, 1024ll * 1024);

    // Stage 3: row softmax over all 3*8*1024 rows
    softmax_kernel<<<3 * 8 * 1024, 256>>>(S);

    // Stage 4: O_r = A_r @ node -> WCAT[:, :, r*768:(r+1)*768]
    for (int r = 0; r < 3; r++)
        sgemm_kernel<false, false><<<dim3(6, 8, 8), blk>>>(
            S + r * SB, node, Wc + r * 768, nullptr, 1024, 1024, 768, 2304,
            1024ll * 1024, 1024ll * 768, 1024ll * 2304, 0);

    // Stage 5: out = WCAT @ params  (M=8192, N=768, K=2304)
    sgemm_kernel<false, false><<<dim3(6, 64, 1), blk>>>(
        Wc, P, out, nullptr, 2304, 2304, 768, 768, 0, 0, 0, 0);
}

// round 7
// speedup vs baseline: 1.4072x; 1.1828x over previous
#include <cuda_runtime.h>
#include <cuda_bf16.h>
#include <cstdint>

typedef unsigned long long u64;
#define SWZ(x) ((x) ^ (((x) >> 3) & 0x70))

// ---------------- device scratch (no runtime allocation allowed) -----------
__device__ __nv_bfloat16 g_nodeA6[37748736];  // node A-ext6 [8192, 4608]
__device__ __nv_bfloat16 g_nodeB6[37748736];  // node B-ext6 [8192, 4608]
__device__ __nv_bfloat16 g_WrT6[10616832];    // W_r^T B-ext6, 3 x [768, 4608]
__device__ __nv_bfloat16 g_Text6[113246208];  // T A-ext6, 3 x [8192, 4608]
__device__ __nv_bfloat16 g_nodeT3[18874368];  // node^T B-ext3, 8 x [768, 3072]
__device__ __nv_bfloat16 g_PT3[5308416];      // P^T B-ext3 [768, 6912]
__device__ __nv_bfloat16 g_Sext3[75497472];   // att A-ext3, 24 x [1024, 3072]
__device__ __nv_bfloat16 g_Wcext3[56623104];  // Wcat A-ext3 [8192, 6912]
__device__ float g_S[25165824];               // scores fp32 [3][8][1024][1024]

// ---------------- helpers ----------------
__device__ __forceinline__ uint32_t smem_u32(const void* p) {
    uint32_t a;
    asm("{ .reg .u64 t; cvta.to.shared.u64 t, %1; cvt.u32.u64 %0, t; }"
        : "=r"(a) : "l"(p));
    return a;
}
__device__ __forceinline__ void ldsm4(uint32_t* r, uint32_t addr) {
    asm volatile("ldmatrix.sync.aligned.m8n8.x4.shared.b16 {%0,%1,%2,%3}, [%4];"
                 : "=r"(r[0]), "=r"(r[1]), "=r"(r[2]), "=r"(r[3]) : "r"(addr));
}
__device__ __forceinline__ void mma16816(float* d, const uint32_t* a,
                                         const uint32_t* b) {
    asm volatile(
        "mma.sync.aligned.m16n8k16.row.col.f32.bf16.bf16.f32 "
        "{%0,%1,%2,%3}, {%4,%5,%6,%7}, {%8,%9}, {%0,%1,%2,%3};"
        : "+f"(d[0]), "+f"(d[1]), "+f"(d[2]), "+f"(d[3])
        : "r"(a[0]), "r"(a[1]), "r"(a[2]), "r"(a[3]), "r"(b[0]), "r"(b[1]));
}
__device__ __forceinline__ void cpasync16(uint32_t dst, const void* src) {
    asm volatile("cp.async.cg.shared.global [%0], [%1], 16;" ::
                 "r"(dst), "l"(src));
}
__device__ __forceinline__ void split3(float v, __nv_bfloat16& a0,
                                       __nv_bfloat16& a1, __nv_bfloat16& a2) {
    a0 = __float2bfloat16(v);
    float r1 = v - __bfloat162float(a0);
    a1 = __float2bfloat16(r1);
    a2 = __float2bfloat16(r1 - __bfloat162float(a1));
}
__device__ __forceinline__ uint32_t bpack(__nv_bfloat16 x, __nv_bfloat16 y) {
    __nv_bfloat162 h;
    h.x = x; h.y = y;
    return *(uint32_t*)&h;
}

// ---------------------------------------------------------------------------
// Extended-K bf16 NT GEMM via mma.sync (base-target tensor path).
// C[128x128 tile] = A[128,Kext] @ B[128,Kext]^T, fp32 accum.
// MODE 0: fp32 store.  MODE 1: fp32 + adjacency mask.
// MODE 2: split3 6-slot A-pattern store.  MODE 3: split2 3-slot A-pattern.
// 256 thr, 8 warps (4 m x 2 n), warp tile 32x64, K-chunk 64, cp.async x2 buf.
// ---------------------------------------------------------------------------
#define SMA(b) ((b) * 32768)
#define SMB(b) ((b) * 32768 + 16384)
#define SM_TOT 65536

template <int MODE>
__global__ void __launch_bounds__(256, 2)
gemm_mma(const __nv_bfloat16* __restrict__ Ag, const __nv_bfloat16* __restrict__ Bg,
         float* __restrict__ Cf, __nv_bfloat16* __restrict__ Cb,
         const int* __restrict__ Adj, int Kext,
         long long sA, long long sB, long long sC, int bmod,
         int ldc, int segK, int colOff, int colStep, int rowMod, int rowMul) {
    extern __shared__ char smem[];
    const uint32_t sbase = smem_u32(smem);
    const int tid = threadIdx.x;
    const int bx = blockIdx.x, by = blockIdx.y, bz = blockIdx.z;

    const __nv_bfloat16* A = Ag + (long long)bz * sA;
    const __nv_bfloat16* B = Bg + (long long)(bz % bmod) * sB;

    // Staging: thread t loads row t>>1, 64B-half t&1, 4 x 16B via cp.async.
    const int srow = tid >> 1, shalf = tid & 1;
    const char* agsrc =
        (const char*)(A + (long long)(by * 128 + srow) * Kext) + shalf * 64;
    const char* bgsrc =
        (const char*)(B + (long long)(bx * 128 + srow) * Kext) + shalf * 64;
    uint32_t sdst[4];
#pragma unroll
    for (int g = 0; g < 4; g++)
        sdst[g] = SWZ(srow * 128 + shalf * 64 + g * 16);

    const int nc = Kext >> 6;

    auto stage = [&](int c) {
        const uint32_t ab = sbase + SMA(c & 1), bb = sbase + SMB(c & 1);
        const char* as = agsrc + (long long)c * 128;
        const char* bs = bgsrc + (long long)c * 128;
#pragma unroll
        for (int g = 0; g < 4; g++) cpasync16(ab + sdst[g], as + g * 16);
#pragma unroll
        for (int g = 0; g < 4; g++) cpasync16(bb + sdst[g], bs + g * 16);
        asm volatile("cp.async.commit_group;");
    };

    // Fragment addressing (SW128): swizzled col j' = j ^ (row & 7), j in 16B.
    const int lane = tid & 31, wid = tid >> 5;
    const int wm = wid & 3, wn = wid >> 2;
    const int ar = wm * 32 + (lane & 7) + ((lane >> 3) & 1) * 8;
    const int ahk = (lane >> 4) & 1, axr = ar & 7;
    const int br = wn * 64 + (lane & 7) + ((lane >> 4) & 1) * 8;
    const int bhk = (lane >> 3) & 1, bxr = br & 7;

    float d[2][8][4];
#pragma unroll
    for (int mt = 0; mt < 2; mt++)
#pragma unroll
        for (int nf = 0; nf < 8; nf++)
#pragma unroll
            for (int i = 0; i < 4; i++) d[mt][nf][i] = 0.0f;

    stage(0);
    if (nc > 1) stage(1);

    for (int c = 0; c < nc; c++) {
        asm volatile("cp.async.wait_group 1;");
        __syncthreads();
        const uint32_t ab = sbase + SMA(c & 1), bb = sbase + SMB(c & 1);
#pragma unroll
        for (int kk = 0; kk < 4; kk++) {
            uint32_t a0[4], a1[4], bq[4][4];
            const uint32_t aoff =
                ab + ar * 128 + (((kk * 2 + ahk) ^ axr) << 4);
            ldsm4(a0, aoff);
            ldsm4(a1, aoff + 16 * 128);
            const uint32_t bcol = ((kk * 2 + bhk) ^ bxr) << 4;
#pragma unroll
            for (int q = 0; q < 4; q++)
                ldsm4(bq[q], bb + (br + q * 16) * 128 + bcol);
#pragma unroll
            for (int q = 0; q < 4; q++)
#pragma unroll
                for (int s = 0; s < 2; s++) {
                    mma16816(d[0][q * 2 + s], a0, &bq[q][s * 2]);
                    mma16816(d[1][q * 2 + s], a1, &bq[q][s * 2]);
                }
        }
        __syncthreads();
        if (c + 2 < nc) stage(c + 2);
    }

    // Epilogue from mma fragment layout: lane holds (row=l>>2 [+8], col=(l&3)*2).
    const int drow = lane >> 2, dcol = (lane & 3) * 2;
#pragma unroll
    for (int mt = 0; mt < 2; mt++)
#pragma unroll
        for (int h = 0; h < 2; h++) {
            const int m = by * 128 + wm * 32 + mt * 16 + drow + h * 8;
#pragma unroll
            for (int nf = 0; nf < 8; nf++) {
                const int n = bx * 128 + wn * 64 + nf * 8 + dcol;
                float v0 = d[mt][nf][h * 2 + 0];
                float v1 = d[mt][nf][h * 2 + 1];
                if (MODE == 0) {
                    float2 s = make_float2(v0, v1);
                    *(float2*)(Cf + (long long)bz * sC + (long long)m * ldc + n) = s;
                } else if (MODE == 1) {
                    const long long off = (long long)bz * sC + (long long)m * ldc + n;
                    int2 mk = *(const int2*)(Adj + off);
                    float2 s;
                    s.x = (mk.x == 1) ? v0 : -1e7f;
                    s.y = (mk.y == 1) ? v1 : -1e7f;
                    *(float2*)(Cf + off) = s;
                } else {
                    const long long rowg =
                        (long long)(bz % rowMod) * rowMul + m;
                    const int colB = colOff + (bz / rowMod) * colStep + n;
                    const int ns = (MODE == 2) ? 6 : 3;
                    __nv_bfloat16* base =
                        Cb + rowg * (long long)(ns * segK) + colB;
                    __nv_bfloat16 x0, x1, x2, y0, y1, y2;
                    split3(v0, x0, x1, x2);
                    split3(v1, y0, y1, y2);
                    const uint32_t p0 = bpack(x0, y0);
                    const uint32_t p1 = bpack(x1, y1);
                    *(uint32_t*)(base) = p0;
                    *(uint32_t*)(base + segK) = p1;
                    *(uint32_t*)(base + 2 * segK) = p0;
                    if (MODE == 2) {
                        const uint32_t p2 = bpack(x2, y2);
                        *(uint32_t*)(base + 3 * segK) = p1;
                        *(uint32_t*)(base + 4 * segK) = p0;
                        *(uint32_t*)(base + 5 * segK) = p2;
                    }
                }
            }
        }
}

// ---------------------------------------------------------------------------
// fp32 [rows,K] -> ext bf16. PAT 0: A-ext6 [a0,a1,a0,a1,a0,a2];
// PAT 1: B-ext6 [b0,b0,b1,b1,b2,b0].
// ---------------------------------------------------------------------------
template <int PAT>
__global__ void kconv_flat(const float* __restrict__ in,
                           __nv_bfloat16* __restrict__ out, int K) {
    const long long i = (long long)blockIdx.x * 256 + threadIdx.x;
    const int row = (int)(i / K), k = (int)(i % K);
    __nv_bfloat16 a0, a1, a2;
    split3(in[i], a0, a1, a2);
    __nv_bfloat16* o = out + (long long)row * 6 * K + k;
    if (PAT == 0) {
        o[0] = a0; o[K] = a1; o[2 * K] = a0;
        o[3 * K] = a1; o[4 * K] = a0; o[5 * K] = a2;
    } else {
        o[0] = a0; o[K] = a0; o[2 * K] = a1;
        o[3 * K] = a1; o[4 * K] = a2; o[5 * K] = a0;
    }
}

// ---------------------------------------------------------------------------
// Transposed B-pattern conversion: out[z][j, slots over k] = split(in[z][k,j]),
// in is [Ko, 768] row-major. PAT 1: B-ext6; PAT 2: B-ext3 [b0,b0,b1].
// ---------------------------------------------------------------------------
template <int PAT>
__global__ void kconv_T(const float* __restrict__ in,
                        __nv_bfloat16* __restrict__ out, int Ko,
                        long long sIn, long long sOut) {
    __shared__ float t[32][33];
    const int tx = threadIdx.x, ty = threadIdx.y;
    const int k0 = blockIdx.x * 32, j0 = blockIdx.y * 32, z = blockIdx.z;
    t[ty][tx] = in[(long long)z * sIn + (long long)(k0 + ty) * 768 + j0 + tx];
    __syncthreads();
    __nv_bfloat16 a0, a1, a2;
    split3(t[tx][ty], a0, a1, a2);  // value at (k0+tx, j0+ty)
    const int ns = (PAT == 1) ? 6 : 3;
    __nv_bfloat16* o = out + (long long)z * sOut +
                       (long long)(j0 + ty) * ns * Ko + (k0 + tx);
    if (PAT == 1) {
        o[0] = a0; o[Ko] = a0; o[2 * Ko] = a1;
        o[3 * Ko] = a1; o[4 * Ko] = a2; o[5 * Ko] = a0;
    } else {
        o[0] = a0; o[Ko] = a0; o[2 * Ko] = a1;
    }
}

// ---------------------------------------------------------------------------
// Row softmax (len 1024) fused with A-ext3 split store ([a0,a1,a0]).
// ---------------------------------------------------------------------------
__global__ void softmax_ext3(const float* __restrict__ S,
                             __nv_bfloat16* __restrict__ E) {
    const long long row = blockIdx.x;
    const float* p = S + row * 1024;
    const int t = threadIdx.x, warp = t >> 5, lane = t & 31;

    float4 v = ((const float4*)p)[t];
    float m = fmaxf(fmaxf(v.x, v.y), fmaxf(v.z, v.w));
#pragma unroll
    for (int o = 16; o; o >>= 1) m = fmaxf(m, __shfl_xor_sync(0xffffffffu, m, o));
    __shared__ float redm[8], reds[8];
    if (lane == 0) redm[warp] = m;
    __syncthreads();
    float mm = redm[0];
#pragma unroll
    for (int i = 1; i < 8; i++) mm = fmaxf(mm, redm[i]);
    v.x = expf(v.x - mm); v.y = expf(v.y - mm);
    v.z = expf(v.z - mm); v.w = expf(v.w - mm);
    float s = v.x + v.y + v.z + v.w;
#pragma unroll
    for (int o = 16; o; o >>= 1) s += __shfl_xor_sync(0xffffffffu, s, o);
    if (lane == 0) reds[warp] = s;
    __syncthreads();
    float ss = reds[0];
#pragma unroll
    for (int i = 1; i < 8; i++) ss += reds[i];
    const float inv = 1.0f / ss;
    float q[4] = {v.x * inv, v.y * inv, v.z * inv, v.w * inv};

    __align__(8) __nv_bfloat16 L0[4], L1[4];
#pragma unroll
    for (int j = 0; j < 4; j++) {
        L0[j] = __float2bfloat16(q[j]);
        L1[j] = __float2bfloat16(q[j] - __bfloat162float(L0[j]));
    }
    __nv_bfloat16* base = E + row * 3072 + t * 4;
    *(uint2*)(base) = *(const uint2*)L0;
    *(uint2*)(base + 1024) = *(const uint2*)L1;
    *(uint2*)(base + 2048) = *(const uint2*)L0;
}

// ---------------------------------------------------------------------------
extern "C" void kernel_launch(void* const* d_in, const int* in_sizes, int n_in,
                              void* d_out, int out_size) {
    const float* node = (const float*)d_in[0];
    const int* adj[3] = {(const int*)d_in[1], (const int*)d_in[2],
                         (const int*)d_in[3]};
    const float* W[3] = {(const float*)d_in[4], (const float*)d_in[5],
                         (const float*)d_in[6]};
    const float* P = (const float*)d_in[7];
    float* out = (float*)d_out;

    void *p0, *p1, *p2, *p3, *p4, *p5, *p6, *p7, *p8;
    cudaGetSymbolAddress(&p0, g_nodeA6);
    cudaGetSymbolAddress(&p1, g_nodeB6);
    cudaGetSymbolAddress(&p2, g_WrT6);
    cudaGetSymbolAddress(&p3, g_Text6);
    cudaGetSymbolAddress(&p4, g_nodeT3);
    cudaGetSymbolAddress(&p5, g_PT3);
    cudaGetSymbolAddress(&p6, g_Sext3);
    cudaGetSymbolAddress(&p7, g_Wcext3);
    cudaGetSymbolAddress(&p8, g_S);
    __nv_bfloat16* nodeA6 = (__nv_bfloat16*)p0;
    __nv_bfloat16* nodeB6 = (__nv_bfloat16*)p1;
    __nv_bfloat16* WrT6 = (__nv_bfloat16*)p2;
    __nv_bfloat16* Text6 = (__nv_bfloat16*)p3;
    __nv_bfloat16* nodeT3 = (__nv_bfloat16*)p4;
    __nv_bfloat16* PT3 = (__nv_bfloat16*)p5;
    __nv_bfloat16* Sext3 = (__nv_bfloat16*)p6;
    __nv_bfloat16* Wcext3 = (__nv_bfloat16*)p7;
    float* S = (float*)p8;

    cudaFuncSetAttribute(gemm_mma<0>, cudaFuncAttributeMaxDynamicSharedMemorySize, SM_TOT);
    cudaFuncSetAttribute(gemm_mma<1>, cudaFuncAttributeMaxDynamicSharedMemorySize, SM_TOT);
    cudaFuncSetAttribute(gemm_mma<2>, cudaFuncAttributeMaxDynamicSharedMemorySize, SM_TOT);
    cudaFuncSetAttribute(gemm_mma<3>, cudaFuncAttributeMaxDynamicSharedMemorySize, SM_TOT);

    dim3 t32(32, 32);
    // Operand conversions.
    kconv_flat<0><<<24576, 256>>>(node, nodeA6, 768);
    kconv_flat<1><<<24576, 256>>>(node, nodeB6, 768);
    for (int r = 0; r < 3; r++)
        kconv_T<1><<<dim3(24, 24, 1), t32>>>(W[r], WrT6 + r * 3538944ll, 768, 0, 0);
    kconv_T<2><<<dim3(32, 24, 8), t32>>>(node, nodeT3, 1024, 786432ll, 2359296ll);
    kconv_T<2><<<dim3(72, 24, 1), t32>>>(P, PT3, 2304, 0, 0);

    // Stage 1: T_r = node @ W_r -> Text6 (A-ext6).  z = relation.
    gemm_mma<2><<<dim3(6, 64, 3), 256, SM_TOT>>>(
        nodeA6, WrT6, nullptr, Text6, nullptr, 4608,
        0, 3538944, 0, 3, 0, 768, 0, 0, 3, 8192);

    // Stage 2: S_r = mask(T_r @ node^T) per batch (z = batch).
    for (int r = 0; r < 3; r++)
        gemm_mma<1><<<dim3(8, 8, 8), 256, SM_TOT>>>(
            Text6 + r * 37748736ll, nodeB6, S + r * 8388608ll, nullptr, adj[r],
            4608, 4718592, 4718592, 1048576, 8, 1024, 0, 0, 0, 1, 0);

    // Stage 3: softmax + A-ext3 split store.
    softmax_ext3<<<24576, 256>>>(S, Sext3);

    // Stage 4: O_r = att_r @ node -> Wcext3 cols r*768..  z = r*8 + b.
    gemm_mma<3><<<dim3(6, 8, 24), 256, SM_TOT>>>(
        Sext3, nodeT3, nullptr, Wcext3, nullptr, 3072,
        3145728, 2359296, 0, 8, 0, 2304, 0, 768, 8, 1024);

    // Stage 5: out = Wcat @ params.
    gemm_mma<0><<<dim3(6, 64, 1), 256, SM_TOT>>>(
        Wcext3, PT3, out, nullptr, nullptr, 6912,
        0, 0, 0, 1, 768, 0, 0, 0, 1, 0);
}

// round 8
// speedup vs baseline: 2.0860x; 1.4823x over previous
#include <cuda_runtime.h>
#include <cuda_fp16.h>
#include <cstdint>

typedef unsigned long long u64;
#define SWZ(x) ((x) ^ (((x) >> 3) & 0x70))

// ---------------- device scratch (no runtime allocation allowed) -----------
// fp16 split-2, 3-slot ext-K scheme: A = [a0, a1, a0], B = [b0, b0, b1];
// sum over slots = a0b0 + a1b0 + a0b1  (drops only a1b1 ~ 2^-22).
__device__ __half g_nodeA3[18874368];  // node A-ext3 [8192, 2304]
__device__ __half g_nodeB3[18874368];  // node B-ext3 [8192, 2304]
__device__ __half g_WrT3[5308416];     // W_r^T B-ext3, 3 x [768, 2304]
__device__ __half g_Text3[56623104];   // T A-ext3, 3 x [8192, 2304]
__device__ __half g_nodeT3[18874368];  // node^T B-ext3, 8 x [768, 3072]
__device__ __half g_PT3[5308416];      // P^T B-ext3 [768, 6912]
__device__ __half g_Sext3[75497472];   // att A-ext3, 24 x [1024, 3072]
__device__ __half g_Wcext3[56623104];  // Wcat A-ext3 [8192, 6912]
__device__ float g_S[25165824];        // scores fp32 [3][8][1024][1024]

// ---------------- helpers ----------------
__device__ __forceinline__ uint32_t smem_u32(const void* p) {
    uint32_t a;
    asm("{ .reg .u64 t; cvta.to.shared.u64 t, %1; cvt.u32.u64 %0, t; }"
        : "=r"(a) : "l"(p));
    return a;
}
__device__ __forceinline__ void ldsm4(uint32_t* r, uint32_t addr) {
    asm volatile("ldmatrix.sync.aligned.m8n8.x4.shared.b16 {%0,%1,%2,%3}, [%4];"
                 : "=r"(r[0]), "=r"(r[1]), "=r"(r[2]), "=r"(r[3]) : "r"(addr));
}
__device__ __forceinline__ void mma16816(float* d, const uint32_t* a,
                                         const uint32_t* b) {
    asm volatile(
        "mma.sync.aligned.m16n8k16.row.col.f32.f16.f16.f32 "
        "{%0,%1,%2,%3}, {%4,%5,%6,%7}, {%8,%9}, {%0,%1,%2,%3};"
        : "+f"(d[0]), "+f"(d[1]), "+f"(d[2]), "+f"(d[3])
        : "r"(a[0]), "r"(a[1]), "r"(a[2]), "r"(a[3]), "r"(b[0]), "r"(b[1]));
}
__device__ __forceinline__ void cpasync16(uint32_t dst, const void* src) {
    asm volatile("cp.async.cg.shared.global [%0], [%1], 16;" ::
                 "r"(dst), "l"(src));
}
__device__ __forceinline__ void split2h(float v, __half& h0, __half& h1) {
    h0 = __float2half(v);
    h1 = __float2half(v - __half2float(h0));
}
__device__ __forceinline__ uint32_t hpack(__half x, __half y) {
    __half2 h;
    h.x = x; h.y = y;
    return *(uint32_t*)&h;
}

// ---------------------------------------------------------------------------
// Extended-K fp16 NT GEMM via mma.sync (base-target tensor path).
// C[128x128 tile] = A[128,Kext] @ B[128,Kext]^T, fp32 accum.
// MODE 0: fp32 store.  MODE 1: fp32 + adjacency mask.
// MODE 2: split2 3-slot A-pattern store ([a0, a1, a0], pitch 3*segK).
// 256 thr, 8 warps (4 m x 2 n), warp tile 32x64, K-chunk 64, cp.async x2 buf.
// ---------------------------------------------------------------------------
#define SMA(b) ((b) * 32768)
#define SMB(b) ((b) * 32768 + 16384)
#define SM_TOT 65536

template <int MODE>
__global__ void __launch_bounds__(256, 2)
gemm_mma(const __half* __restrict__ Ag, const __half* __restrict__ Bg,
         float* __restrict__ Cf, __half* __restrict__ Cb,
         const int* __restrict__ Adj, int Kext,
         long long sA, long long sB, long long sC, int bmod,
         int ldc, int segK, int colOff, int colStep, int rowMod, int rowMul) {
    extern __shared__ char smem[];
    const uint32_t sbase = smem_u32(smem);
    const int tid = threadIdx.x;
    const int bx = blockIdx.x, by = blockIdx.y, bz = blockIdx.z;

    const __half* A = Ag + (long long)bz * sA;
    const __half* B = Bg + (long long)(bz % bmod) * sB;

    // Staging: thread t loads row t>>1, 64B-half t&1, 4 x 16B via cp.async.
    const int srow = tid >> 1, shalf = tid & 1;
    const char* agsrc =
        (const char*)(A + (long long)(by * 128 + srow) * Kext) + shalf * 64;
    const char* bgsrc =
        (const char*)(B + (long long)(bx * 128 + srow) * Kext) + shalf * 64;
    uint32_t sdst[4];
#pragma unroll
    for (int g = 0; g < 4; g++)
        sdst[g] = SWZ(srow * 128 + shalf * 64 + g * 16);

    const int nc = Kext >> 6;

    auto stage = [&](int c) {
        const uint32_t ab = sbase + SMA(c & 1), bb = sbase + SMB(c & 1);
        const char* as = agsrc + (long long)c * 128;
        const char* bs = bgsrc + (long long)c * 128;
#pragma unroll
        for (int g = 0; g < 4; g++) cpasync16(ab + sdst[g], as + g * 16);
#pragma unroll
        for (int g = 0; g < 4; g++) cpasync16(bb + sdst[g], bs + g * 16);
        asm volatile("cp.async.commit_group;");
    };

    // Fragment addressing (SW128): swizzled col j' = j ^ (row & 7), j in 16B.
    const int lane = tid & 31, wid = tid >> 5;
    const int wm = wid & 3, wn = wid >> 2;
    const int ar = wm * 32 + (lane & 7) + ((lane >> 3) & 1) * 8;
    const int ahk = (lane >> 4) & 1, axr = ar & 7;
    const int br = wn * 64 + (lane & 7) + ((lane >> 4) & 1) * 8;
    const int bhk = (lane >> 3) & 1, bxr = br & 7;

    float d[2][8][4];
#pragma unroll
    for (int mt = 0; mt < 2; mt++)
#pragma unroll
        for (int nf = 0; nf < 8; nf++)
#pragma unroll
            for (int i = 0; i < 4; i++) d[mt][nf][i] = 0.0f;

    stage(0);
    if (nc > 1) stage(1);

    for (int c = 0; c < nc; c++) {
        asm volatile("cp.async.wait_group 1;");
        __syncthreads();
        const uint32_t ab = sbase + SMA(c & 1), bb = sbase + SMB(c & 1);
#pragma unroll
        for (int kk = 0; kk < 4; kk++) {
            uint32_t a0[4], a1[4], bq[4][4];
            const uint32_t aoff =
                ab + ar * 128 + (((kk * 2 + ahk) ^ axr) << 4);
            ldsm4(a0, aoff);
            ldsm4(a1, aoff + 16 * 128);
            const uint32_t bcol = ((kk * 2 + bhk) ^ bxr) << 4;
#pragma unroll
            for (int q = 0; q < 4; q++)
                ldsm4(bq[q], bb + (br + q * 16) * 128 + bcol);
#pragma unroll
            for (int q = 0; q < 4; q++)
#pragma unroll
                for (int s = 0; s < 2; s++) {
                    mma16816(d[0][q * 2 + s], a0, &bq[q][s * 2]);
                    mma16816(d[1][q * 2 + s], a1, &bq[q][s * 2]);
                }
        }
        __syncthreads();
        if (c + 2 < nc) stage(c + 2);
    }

    // Epilogue from mma fragment layout: lane holds (row=l>>2 [+8], col=(l&3)*2).
    const int drow = lane >> 2, dcol = (lane & 3) * 2;
#pragma unroll
    for (int mt = 0; mt < 2; mt++)
#pragma unroll
        for (int h = 0; h < 2; h++) {
            const int m = by * 128 + wm * 32 + mt * 16 + drow + h * 8;
#pragma unroll
            for (int nf = 0; nf < 8; nf++) {
                const int n = bx * 128 + wn * 64 + nf * 8 + dcol;
                float v0 = d[mt][nf][h * 2 + 0];
                float v1 = d[mt][nf][h * 2 + 1];
                if (MODE == 0) {
                    float2 s = make_float2(v0, v1);
                    *(float2*)(Cf + (long long)bz * sC + (long long)m * ldc + n) = s;
                } else if (MODE == 1) {
                    const long long off = (long long)bz * sC + (long long)m * ldc + n;
                    int2 mk = *(const int2*)(Adj + off);
                    float2 s;
                    s.x = (mk.x == 1) ? v0 : -1e7f;
                    s.y = (mk.y == 1) ? v1 : -1e7f;
                    *(float2*)(Cf + off) = s;
                } else {
                    const long long rowg =
                        (long long)(bz % rowMod) * rowMul + m;
                    const int colB = colOff + (bz / rowMod) * colStep + n;
                    __half* base = Cb + rowg * (long long)(3 * segK) + colB;
                    __half x0, x1, y0, y1;
                    split2h(v0, x0, x1);
                    split2h(v1, y0, y1);
                    const uint32_t p0 = hpack(x0, y0);
                    const uint32_t p1 = hpack(x1, y1);
                    *(uint32_t*)(base) = p0;
                    *(uint32_t*)(base + segK) = p1;
                    *(uint32_t*)(base + 2 * segK) = p0;
                }
            }
        }
}

// ---------------------------------------------------------------------------
// fp32 [rows,K] -> ext3 fp16. PAT 0: A-ext3 [a0,a1,a0]; PAT 1: B-ext3 [b0,b0,b1].
// ---------------------------------------------------------------------------
template <int PAT>
__global__ void kconv_flat(const float* __restrict__ in,
                           __half* __restrict__ out, int K) {
    const long long i = (long long)blockIdx.x * 256 + threadIdx.x;
    const int row = (int)(i / K), k = (int)(i % K);
    __half a0, a1;
    split2h(in[i], a0, a1);
    __half* o = out + (long long)row * 3 * K + k;
    if (PAT == 0) {
        o[0] = a0; o[K] = a1; o[2 * K] = a0;
    } else {
        o[0] = a0; o[K] = a0; o[2 * K] = a1;
    }
}

// ---------------------------------------------------------------------------
// Transposed B-ext3 conversion: out[z][j, {k, Ko+k, 2Ko+k}] = [b0,b0,b1] of
// in[z][k*768 + j];  in is [Ko, 768] row-major.  Block (32,32).
// ---------------------------------------------------------------------------
__global__ void kconv_T(const float* __restrict__ in,
                        __half* __restrict__ out, int Ko,
                        long long sIn, long long sOut) {
    __shared__ float t[32][33];
    const int tx = threadIdx.x, ty = threadIdx.y;
    const int k0 = blockIdx.x * 32, j0 = blockIdx.y * 32, z = blockIdx.z;
    t[ty][tx] = in[(long long)z * sIn + (long long)(k0 + ty) * 768 + j0 + tx];
    __syncthreads();
    __half b0, b1;
    split2h(t[tx][ty], b0, b1);  // value at (k0+tx, j0+ty)
    __half* o = out + (long long)z * sOut +
                (long long)(j0 + ty) * 3 * Ko + (k0 + tx);
    o[0] = b0; o[Ko] = b0; o[2 * Ko] = b1;
}

// ---------------------------------------------------------------------------
// Row softmax (len 1024) fused with A-ext3 split store ([a0,a1,a0]).
// ---------------------------------------------------------------------------
__global__ void softmax_ext3(const float* __restrict__ S,
                             __half* __restrict__ E) {
    const long long row = blockIdx.x;
    const float* p = S + row * 1024;
    const int t = threadIdx.x, warp = t >> 5, lane = t & 31;

    float4 v = ((const float4*)p)[t];
    float m = fmaxf(fmaxf(v.x, v.y), fmaxf(v.z, v.w));
#pragma unroll
    for (int o = 16; o; o >>= 1) m = fmaxf(m, __shfl_xor_sync(0xffffffffu, m, o));
    __shared__ float redm[8], reds[8];
    if (lane == 0) redm[warp] = m;
    __syncthreads();
    float mm = redm[0];
#pragma unroll
    for (int i = 1; i < 8; i++) mm = fmaxf(mm, redm[i]);
    v.x = expf(v.x - mm); v.y = expf(v.y - mm);
    v.z = expf(v.z - mm); v.w = expf(v.w - mm);
    float s = v.x + v.y + v.z + v.w;
#pragma unroll
    for (int o = 16; o; o >>= 1) s += __shfl_xor_sync(0xffffffffu, s, o);
    if (lane == 0) reds[warp] = s;
    __syncthreads();
    float ss = reds[0];
#pragma unroll
    for (int i = 1; i < 8; i++) ss += reds[i];
    const float inv = 1.0f / ss;
    float q[4] = {v.x * inv, v.y * inv, v.z * inv, v.w * inv};

    __align__(8) __half L0[4], L1[4];
#pragma unroll
    for (int j = 0; j < 4; j++) split2h(q[j], L0[j], L1[j]);
    __half* base = E + row * 3072 + t * 4;
    *(uint2*)(base) = *(const uint2*)L0;
    *(uint2*)(base + 1024) = *(const uint2*)L1;
    *(uint2*)(base + 2048) = *(const uint2*)L0;
}

// ---------------------------------------------------------------------------
extern "C" void kernel_launch(void* const* d_in, const int* in_sizes, int n_in,
                              void* d_out, int out_size) {
    const float* node = (const float*)d_in[0];
    const int* adj[3] = {(const int*)d_in[1], (const int*)d_in[2],
                         (const int*)d_in[3]};
    const float* W[3] = {(const float*)d_in[4], (const float*)d_in[5],
                         (const float*)d_in[6]};
    const float* P = (const float*)d_in[7];
    float* out = (float*)d_out;

    void *p0, *p1, *p2, *p3, *p4, *p5, *p6, *p7, *p8;
    cudaGetSymbolAddress(&p0, g_nodeA3);
    cudaGetSymbolAddress(&p1, g_nodeB3);
    cudaGetSymbolAddress(&p2, g_WrT3);
    cudaGetSymbolAddress(&p3, g_Text3);
    cudaGetSymbolAddress(&p4, g_nodeT3);
    cudaGetSymbolAddress(&p5, g_PT3);
    cudaGetSymbolAddress(&p6, g_Sext3);
    cudaGetSymbolAddress(&p7, g_Wcext3);
    cudaGetSymbolAddress(&p8, g_S);
    __half* nodeA3 = (__half*)p0;
    __half* nodeB3 = (__half*)p1;
    __half* WrT3 = (__half*)p2;
    __half* Text3 = (__half*)p3;
    __half* nodeT3 = (__half*)p4;
    __half* PT3 = (__half*)p5;
    __half* Sext3 = (__half*)p6;
    __half* Wcext3 = (__half*)p7;
    float* S = (float*)p8;

    cudaFuncSetAttribute(gemm_mma<0>, cudaFuncAttributeMaxDynamicSharedMemorySize, SM_TOT);
    cudaFuncSetAttribute(gemm_mma<1>, cudaFuncAttributeMaxDynamicSharedMemorySize, SM_TOT);
    cudaFuncSetAttribute(gemm_mma<2>, cudaFuncAttributeMaxDynamicSharedMemorySize, SM_TOT);

    dim3 t32(32, 32);
    // Operand conversions (fp16 split-2, 3-slot).
    kconv_flat<0><<<24576, 256>>>(node, nodeA3, 768);
    kconv_flat<1><<<24576, 256>>>(node, nodeB3, 768);
    for (int r = 0; r < 3; r++)
        kconv_T<<<dim3(24, 24, 1), t32>>>(W[r], WrT3 + r * 1769472ll, 768, 0, 0);
    kconv_T<<<dim3(32, 24, 8), t32>>>(node, nodeT3, 1024, 786432ll, 2359296ll);
    kconv_T<<<dim3(72, 24, 1), t32>>>(P, PT3, 2304, 0, 0);

    // Stage 1: T_r = node @ W_r -> Text3 (A-ext3).  z = relation.
    gemm_mma<2><<<dim3(6, 64, 3), 256, SM_TOT>>>(
        nodeA3, WrT3, nullptr, Text3, nullptr, 2304,
        0, 1769472, 0, 3, 0, 768, 0, 0, 3, 8192);

    // Stage 2: S_r = mask(T_r @ node^T) per batch (z = batch).
    for (int r = 0; r < 3; r++)
        gemm_mma<1><<<dim3(8, 8, 8), 256, SM_TOT>>>(
            Text3 + r * 18874368ll, nodeB3, S + r * 8388608ll, nullptr, adj[r],
            2304, 2359296, 2359296, 1048576, 8, 1024, 0, 0, 0, 1, 0);

    // Stage 3: softmax + A-ext3 split store.
    softmax_ext3<<<24576, 256>>>(S, Sext3);

    // Stage 4: O_r = att_r @ node -> Wcext3 cols r*768..  z = r*8 + b.
    gemm_mma<2><<<dim3(6, 8, 24), 256, SM_TOT>>>(
        Sext3, nodeT3, nullptr, Wcext3, nullptr, 3072,
        3145728, 2359296, 0, 8, 0, 2304, 0, 768, 8, 1024);

    // Stage 5: out = Wcat @ params.
    gemm_mma<0><<<dim3(6, 64, 1), 256, SM_TOT>>>(
        Wcext3, PT3, out, nullptr, nullptr, 6912,
        0, 0, 0, 1, 768, 0, 0, 0, 1, 0);
}